// round 1
// baseline (speedup 1.0000x reference)
#include <cuda_runtime.h>
#include <math.h>

// ---------------------------------------------------------------------------
// Problem constants (from reference)
// ---------------------------------------------------------------------------
#define D_ID   32
#define D_TR   32
#define D_IN   64          // D_ID + D_TR
#define HID    256
#define KBINS  8
#define PCH    25          // 3*K + 1 params per channel
#define NPAR   800         // D_TR * PCH
#define BMAX   131072

#define MINW   0.001f
#define MIND   0.001f
#define EPSC   1e-12f

// Scratch (allocation-free rule: __device__ globals)
__device__ float g_H[(size_t)BMAX * HID];            // 134 MB
__device__ float g_P[(size_t)BMAX * NPAR];           // 419 MB

// ---------------------------------------------------------------------------
// Kernel 1: H = relu(X[:, :32] @ W1 + b1)
// Block: 256 threads, 64 rows. thread tile: 4 rows x 16 cols.
// ---------------------------------------------------------------------------
__global__ __launch_bounds__(256, 2)
void k1_gemm1(const float* __restrict__ X,
              const float* __restrict__ W1,
              const float* __restrict__ b1, int B)
{
    __shared__ float Xs[D_ID * 68];      // [k][r], r-stride 68 (16B aligned, 4-way ok)
    __shared__ float W1s[D_ID * HID];    // [k][j], same layout as gmem

    const int tid   = threadIdx.x;
    const int rbase = blockIdx.x * 64;

    for (int i = tid; i < D_ID * HID; i += 256) W1s[i] = W1[i];
    for (int i = tid; i < 64 * D_ID; i += 256) {
        int r = i >> 5, k = i & 31;
        Xs[k * 68 + r] = X[(size_t)(rbase + r) * D_IN + k];
    }
    __syncthreads();

    const int ty = tid >> 4;   // 0..15 (row group of 4)
    const int tx = tid & 15;   // 0..15 (col group of 16)

    float bb[16];
#pragma unroll
    for (int j = 0; j < 16; j++) bb[j] = b1[tx * 16 + j];

    float acc[4][16];
#pragma unroll
    for (int i = 0; i < 4; i++)
#pragma unroll
        for (int j = 0; j < 16; j++) acc[i][j] = bb[j];

#pragma unroll
    for (int k = 0; k < D_ID; k++) {
        float4 a = *(const float4*)&Xs[k * 68 + ty * 4];
        const float* wp = &W1s[k * HID + tx * 16];
        float4 b0 = *(const float4*)(wp);
        float4 b1v = *(const float4*)(wp + 4);
        float4 b2v = *(const float4*)(wp + 8);
        float4 b3v = *(const float4*)(wp + 12);
        float av[4] = {a.x, a.y, a.z, a.w};
        float bv[16] = {b0.x, b0.y, b0.z, b0.w, b1v.x, b1v.y, b1v.z, b1v.w,
                        b2v.x, b2v.y, b2v.z, b2v.w, b3v.x, b3v.y, b3v.z, b3v.w};
#pragma unroll
        for (int i = 0; i < 4; i++)
#pragma unroll
            for (int j = 0; j < 16; j++) acc[i][j] = fmaf(av[i], bv[j], acc[i][j]);
    }

#pragma unroll
    for (int i = 0; i < 4; i++) {
        size_t off = (size_t)(rbase + ty * 4 + i) * HID + tx * 16;
#pragma unroll
        for (int j4 = 0; j4 < 4; j4++) {
            float4 v;
            v.x = fmaxf(acc[i][j4 * 4 + 0], 0.f);
            v.y = fmaxf(acc[i][j4 * 4 + 1], 0.f);
            v.z = fmaxf(acc[i][j4 * 4 + 2], 0.f);
            v.w = fmaxf(acc[i][j4 * 4 + 3], 0.f);
            *(float4*)&g_H[off + j4 * 4] = v;
        }
    }
}

// ---------------------------------------------------------------------------
// Kernel 2: P = H @ W2   (M=B, N=800, K=256)
// Block: 256 threads, BM=128 rows. N looped inside block in 7 tiles of 128.
// Thread tile 8x8. H tile fully resident in smem (transposed, pad 132).
// ---------------------------------------------------------------------------
#define BM2  128
#define BN2  128
#define KC2  32
#define HPAD 132

__global__ __launch_bounds__(256, 1)
void k2_gemm2(const float* __restrict__ W2, int B)
{
    extern __shared__ float sm[];
    float* Hs  = sm;                 // [256][HPAD]
    float* W2s = sm + HID * HPAD;    // [KC2][BN2]

    const int tid   = threadIdx.x;
    const int rbase = blockIdx.x * BM2;

    for (int i = tid; i < BM2 * HID; i += 256) {
        int r = i >> 8, k = i & 255;
        Hs[k * HPAD + r] = g_H[(size_t)(rbase + r) * HID + k];
    }
    __syncthreads();

    const int ty = tid >> 4;   // 0..15 -> rows ty*8..ty*8+7
    const int tx = tid & 15;   // 0..15 -> cols tx*8..tx*8+7

    for (int nt = 0; nt < 7; nt++) {
        const int nbase = nt * BN2;

        float acc[8][8];
#pragma unroll
        for (int i = 0; i < 8; i++)
#pragma unroll
            for (int j = 0; j < 8; j++) acc[i][j] = 0.f;

        for (int kc = 0; kc < HID; kc += KC2) {
            for (int i = tid; i < KC2 * BN2; i += 256) {
                int kk = i >> 7, c = i & 127;
                int col = nbase + c;
                W2s[kk * BN2 + c] = (col < NPAR)
                    ? W2[(size_t)(kc + kk) * NPAR + col] : 0.f;
            }
            __syncthreads();

#pragma unroll 8
            for (int kk = 0; kk < KC2; kk++) {
                const float* hp = &Hs[(kc + kk) * HPAD + ty * 8];
                float4 a0 = *(const float4*)(hp);
                float4 a1 = *(const float4*)(hp + 4);
                const float* wp = &W2s[kk * BN2 + tx * 8];
                float4 b0 = *(const float4*)(wp);
                float4 b1v = *(const float4*)(wp + 4);
                float av[8] = {a0.x, a0.y, a0.z, a0.w, a1.x, a1.y, a1.z, a1.w};
                float bv[8] = {b0.x, b0.y, b0.z, b0.w, b1v.x, b1v.y, b1v.z, b1v.w};
#pragma unroll
                for (int i = 0; i < 8; i++)
#pragma unroll
                    for (int j = 0; j < 8; j++)
                        acc[i][j] = fmaf(av[i], bv[j], acc[i][j]);
            }
            __syncthreads();
        }

        // store (predicated for last partial tile: cols 768..799 only)
        const int c0 = nbase + tx * 8;
#pragma unroll
        for (int i = 0; i < 8; i++) {
            size_t rowoff = (size_t)(rbase + ty * 8 + i) * NPAR;
            if (c0 < NPAR) {
                float4 v = make_float4(acc[i][0], acc[i][1], acc[i][2], acc[i][3]);
                *(float4*)&g_P[rowoff + c0] = v;
            }
            if (c0 + 4 < NPAR) {
                float4 v = make_float4(acc[i][4], acc[i][5], acc[i][6], acc[i][7]);
                *(float4*)&g_P[rowoff + c0 + 4] = v;
            }
        }
    }
}

// ---------------------------------------------------------------------------
// Kernel 3: spline epilogue. warp = row, lane = channel.
// out[0 .. B*64)  : concat(identity, y)
// out[B*64 .. B*65): logabsdet
// ---------------------------------------------------------------------------
__device__ __forceinline__ float softplusf(float x) {
    return fmaxf(x, 0.f) + log1pf(expf(-fabsf(x)));
}

__global__ __launch_bounds__(256, 4)
void k3_spline(const float* __restrict__ X,
               const float* __restrict__ b2,
               float* __restrict__ out, int B)
{
    const int row  = blockIdx.x * 8 + (threadIdx.x >> 5);
    const int lane = threadIdx.x & 31;

    const float* xr = X + (size_t)row * D_IN;
    // identity copy
    out[(size_t)row * D_IN + lane] = xr[lane];

    const float x = xr[D_ID + lane];

    const float* pp = g_P + (size_t)row * NPAR + lane * PCH;
    const float* bp = b2 + lane * PCH;
    float pr[PCH];
#pragma unroll
    for (int j = 0; j < PCH; j++) pr[j] = pp[j] + bp[j];

    // --- widths: softmax -> affine -> cumsum -> renormalize ---
    float mw = pr[0];
#pragma unroll
    for (int j = 1; j < 8; j++) mw = fmaxf(mw, pr[j]);
    float ew[8], sw = 0.f;
#pragma unroll
    for (int j = 0; j < 8; j++) { ew[j] = expf(pr[j] - mw); sw += ew[j]; }
    float invw = 1.f / sw;
    float w[8];
#pragma unroll
    for (int j = 0; j < 8; j++) w[j] = MINW + (1.f - MINW * 8.f) * ew[j] * invw;
    float cw[9];
    cw[0] = 0.f;
#pragma unroll
    for (int j = 0; j < 8; j++) cw[j + 1] = cw[j] + w[j];
    float itw = 1.f / fmaxf(cw[8], EPSC);
#pragma unroll
    for (int j = 0; j < 9; j++) cw[j] *= itw;
#pragma unroll
    for (int j = 0; j < 8; j++) w[j] = cw[j + 1] - cw[j];

    // --- heights ---
    float mh = pr[8];
#pragma unroll
    for (int j = 1; j < 8; j++) mh = fmaxf(mh, pr[8 + j]);
    float eh[8], sh = 0.f;
#pragma unroll
    for (int j = 0; j < 8; j++) { eh[j] = expf(pr[8 + j] - mh); sh += eh[j]; }
    float invh = 1.f / sh;
    float h[8];
#pragma unroll
    for (int j = 0; j < 8; j++) h[j] = MINW + (1.f - MINW * 8.f) * eh[j] * invh;
    float chh[9];
    chh[0] = 0.f;
#pragma unroll
    for (int j = 0; j < 8; j++) chh[j + 1] = chh[j] + h[j];
    float ith = 1.f / fmaxf(chh[8], EPSC);
#pragma unroll
    for (int j = 0; j < 9; j++) chh[j] *= ith;
#pragma unroll
    for (int j = 0; j < 8; j++) h[j] = chh[j + 1] - chh[j];

    // --- derivatives ---
    float d[9];
#pragma unroll
    for (int j = 0; j < 9; j++) d[j] = MIND + softplusf(pr[16 + j]);

    // --- RQS forward ---
    const bool inside = (x >= -10.f) && (x <= 10.f);
    float xs = fminf(fmaxf((x + 10.f) * 0.05f, 0.f), 1.f);

    float xk = cw[0], wk = w[0], yk = chh[0], hk = h[0], dk = d[0], dk1 = d[1];
#pragma unroll
    for (int i = 0; i < 8; i++) {
        if (xs >= cw[i]) {
            xk = cw[i]; wk = w[i]; yk = chh[i]; hk = h[i]; dk = d[i]; dk1 = d[i + 1];
        }
    }

    float t   = fminf(fmaxf((xs - xk) / (wk + EPSC), 0.f), 1.f);
    float a   = (hk + EPSC) / (wk + EPSC);
    float bb  = dk;
    float cc  = dk1;
    float omt = 1.f - t;
    float num = a * t * t + bb * t * omt;
    float den = a + (bb + cc - 2.f * a) * t * omt;
    float s   = num / (den + EPSC);
    float y   = (yk + hk * s) * 20.f - 10.f;

    float dnum = a * a * (cc * t * t + 2.f * a * t * omt + bb * omt * omt);
    float dydx = dnum / (den * den + EPSC);
    float lad  = logf(fmaxf(dydx, 1e-12f));

    float yout = inside ? y : x;
    float ladc = inside ? lad : 0.f;

    out[(size_t)row * D_IN + D_ID + lane] = yout;

#pragma unroll
    for (int o = 16; o; o >>= 1)
        ladc += __shfl_xor_sync(0xffffffffu, ladc, o);
    if (lane == 0) out[(size_t)B * D_IN + row] = ladc;
}

// ---------------------------------------------------------------------------
extern "C" void kernel_launch(void* const* d_in, const int* in_sizes, int n_in,
                              void* d_out, int out_size)
{
    const float* X  = (const float*)d_in[0];
    const float* W1 = (const float*)d_in[1];
    const float* b1 = (const float*)d_in[2];
    const float* W2 = (const float*)d_in[3];
    const float* b2 = (const float*)d_in[4];
    float* out = (float*)d_out;

    const int B = in_sizes[0] / D_IN;

    const int smem2 = (HID * HPAD + KC2 * BN2) * (int)sizeof(float); // ~151.5 KB
    cudaFuncSetAttribute(k2_gemm2, cudaFuncAttributeMaxDynamicSharedMemorySize, smem2);

    k1_gemm1<<<B / 64, 256>>>(X, W1, b1, B);
    k2_gemm2<<<B / 128, 256, smem2>>>(W2, B);
    k3_spline<<<B / 8, 256>>>(X, b2, out, B);
}

// round 4
// speedup vs baseline: 3.4224x; 3.4224x over previous
#include <cuda_runtime.h>
#include <cuda_fp16.h>
#include <math.h>
#include <stdint.h>

// ---------------------------------------------------------------------------
// Problem constants
// ---------------------------------------------------------------------------
#define D_IN   64
#define HID    256
#define NPAR   800
#define MINW   0.001f
#define MIND   0.001f
#define EPSC   1e-12f

// Prepared weights (fp16 hi/lo splits, transposed to [n][k])
__device__ __half g_W1h[HID * 32],  g_W1l[HID * 32];
__device__ __half g_W2h[NPAR * HID], g_W2l[NPAR * HID];

// ---------------------------------------------------------------------------
// smem layout (bytes)
// ---------------------------------------------------------------------------
#define OFF_AH   0                    // A (H) hi : 128 rows x 512B (swizzled)
#define OFF_AL   65536                // A lo
#define OFF_U    131072               // union region, 51200 B
#define OFF_XH   (OFF_U)              // phase1: X hi  128x64B
#define OFF_XL   (OFF_U + 8192)
#define OFF_W1H  (OFF_U + 16384)     // phase1: W1t hi 256x64B
#define OFF_W1L  (OFF_U + 32768)
#define BUFSZ    25600                // phase2: W2 chunk buf (hi 12800 + lo 12800)
#define OFF_B2   182272               // 800 f
#define OFF_B1   185472               // 256 f
#define OFF_LAD  186496               // 128 f
#define SMEM_TOT 187008

// ---------------------------------------------------------------------------
// helpers
// ---------------------------------------------------------------------------
__device__ __forceinline__ uint32_t smem_u32(const void* p) {
    uint32_t a;
    asm("{ .reg .u64 t; cvta.to.shared.u64 t, %1; cvt.u32.u64 %0, t; }" : "=r"(a) : "l"(p));
    return a;
}
__device__ __forceinline__ void ldsm4(uint32_t r[4], uint32_t addr) {
    asm volatile("ldmatrix.sync.aligned.m8n8.x4.shared.b16 {%0,%1,%2,%3}, [%4];"
                 : "=r"(r[0]), "=r"(r[1]), "=r"(r[2]), "=r"(r[3]) : "r"(addr));
}
__device__ __forceinline__ void mma16816(float c[4], const uint32_t a[4], const uint32_t b[2]) {
    asm volatile("mma.sync.aligned.m16n8k16.row.col.f32.f16.f16.f32 "
                 "{%0,%1,%2,%3}, {%4,%5,%6,%7}, {%8,%9}, {%0,%1,%2,%3};"
                 : "+f"(c[0]), "+f"(c[1]), "+f"(c[2]), "+f"(c[3])
                 : "r"(a[0]), "r"(a[1]), "r"(a[2]), "r"(a[3]), "r"(b[0]), "r"(b[1]));
}
__device__ __forceinline__ uint32_t packh2(float v0, float v1) {
    __half h0 = __float2half_rn(v0), h1 = __float2half_rn(v1);
    return (uint32_t)__half_as_ushort(h0) | ((uint32_t)__half_as_ushort(h1) << 16);
}

// A region (512B rows): byte = r*512 + ((g ^ (r&7))<<4) + within; g = 16B group 0..31
__device__ __forceinline__ uint32_t aoff(int r, int g) {
    return (uint32_t)(r * 512 + ((g ^ (r & 7)) << 4));
}
// 64B-row regions (X, W1t, W2 chunks): byte = n*64 + ((g ^ ((n>>1)&3))<<4); g 0..3
__device__ __forceinline__ uint32_t boff(int n, int g) {
    return (uint32_t)(n * 64 + ((g ^ ((n >> 1) & 3)) << 4));
}

// ---------------------------------------------------------------------------
// prep: transpose + fp16-split W1, W2
// ---------------------------------------------------------------------------
__global__ void kprep(const float* __restrict__ W1, const float* __restrict__ W2) {
    int n = blockIdx.x, k = threadIdx.x;
    if (n < NPAR) {
        float v = W2[(size_t)k * NPAR + n];
        __half h = __float2half_rn(v);
        g_W2h[n * HID + k] = h;
        g_W2l[n * HID + k] = __float2half_rn(v - __half2float(h));
    } else {
        int nn = n - NPAR;
        if (k < 32) {
            float v = W1[k * HID + nn];
            __half h = __float2half_rn(v);
            g_W1h[nn * 32 + k] = h;
            g_W1l[nn * 32 + k] = __float2half_rn(v - __half2float(h));
        }
    }
}

// ---------------------------------------------------------------------------
// fused kernel: 512 threads, 128 rows per CTA
// ---------------------------------------------------------------------------
__global__ __launch_bounds__(512, 1)
void kmain(const float* __restrict__ X,
           const float* __restrict__ b1,
           const float* __restrict__ b2,
           float* __restrict__ out, int B)
{
    extern __shared__ char sm[];
    const uint32_t sb = smem_u32(sm);
    const int tid = threadIdx.x, lane = tid & 31, wid = tid >> 5;
    const int wm = wid >> 2, wn = wid & 3;
    const int rbase = blockIdx.x * 128;

    float* b1s   = (float*)(sm + OFF_B1);
    float* b2s   = (float*)(sm + OFF_B2);
    float* lad   = (float*)(sm + OFF_LAD);
    float* stage = (float*)(sm + OFF_U);

    // ---- init ----
    if (tid < 256) b1s[tid] = b1[tid];
    for (int i = tid; i < NPAR; i += 512) b2s[i] = b2[i];
    if (tid < 128) lad[tid] = 0.f;
    // identity copy (cols 0..31)
    for (int i = tid; i < 1024; i += 512) {
        int r = i >> 3, q = i & 7;
        ((float4*)(out + (size_t)(rbase + r) * D_IN))[q] =
            ((const float4*)(X + (size_t)(rbase + r) * D_IN))[q];
    }

    // ---- phase-1 operand staging: X split + W1t ----
    {
        int r = tid >> 2, q = tid & 3;
        const float* xp = X + (size_t)(rbase + r) * D_IN + q * 8;
        float4 v0 = *(const float4*)xp, v1 = *(const float4*)(xp + 4);
        float vv[8] = {v0.x, v0.y, v0.z, v0.w, v1.x, v1.y, v1.z, v1.w};
        ushort hh[8], hl[8];
#pragma unroll
        for (int j = 0; j < 8; j++) {
            __half h = __float2half_rn(vv[j]);
            hh[j] = __half_as_ushort(h);
            hl[j] = __half_as_ushort(__float2half_rn(vv[j] - __half2float(h)));
        }
        uint32_t off = boff(r, q);
        *(uint4*)(sm + OFF_XH + off) = *(uint4*)hh;
        *(uint4*)(sm + OFF_XL + off) = *(uint4*)hl;
    }
#pragma unroll
    for (int s = 0; s < 4; s++) {
        int i = tid + s * 512;          // 2048 = 2 splits x 256 rows x 4 groups
        int split = i >> 10, ii = i & 1023;
        int n = ii >> 2, g = ii & 3;
        const __half* src = split ? g_W1l : g_W1h;
        uint4 v = *(const uint4*)(src + n * 32 + g * 8);
        *(uint4*)(sm + (split ? OFF_W1L : OFF_W1H) + boff(n, g)) = v;
    }
    __syncthreads();

    // ---- phase-1 mma: H = relu(X @ W1 + b1), warp tile m32 x n64 ----
    float acc1[2][8][4];
#pragma unroll
    for (int i = 0; i < 2; i++)
#pragma unroll
        for (int j = 0; j < 8; j++)
#pragma unroll
            for (int c = 0; c < 4; c++) acc1[i][j][c] = 0.f;

#pragma unroll
    for (int t = 0; t < 2; t++) {
        uint32_t aH[2][4], aL[2][4], bb[8][2];
#pragma unroll
        for (int i = 0; i < 2; i++) {
            int r = wm * 32 + i * 16 + (lane & 15);
            int g = 2 * t + (lane >> 4);
            ldsm4(aH[i], sb + OFF_XH + boff(r, g));
            ldsm4(aL[i], sb + OFF_XL + boff(r, g));
        }
#pragma unroll
        for (int p = 0; p < 4; p++) {
            int jj = wn * 8 + ((lane < 16) ? 2 * p : 2 * p + 1);
            int n = jj * 8 + (lane & 7);
            int g = 2 * t + ((lane >> 3) & 1);
            uint32_t r4[4];
            ldsm4(r4, sb + OFF_W1H + boff(n, g));
            bb[2 * p][0] = r4[0]; bb[2 * p][1] = r4[1];
            bb[2 * p + 1][0] = r4[2]; bb[2 * p + 1][1] = r4[3];
        }
#pragma unroll
        for (int i = 0; i < 2; i++)
#pragma unroll
            for (int j = 0; j < 8; j++) {
                mma16816(acc1[i][j], aH[i], bb[j]);
                mma16816(acc1[i][j], aL[i], bb[j]);
            }
#pragma unroll
        for (int p = 0; p < 4; p++) {
            int jj = wn * 8 + ((lane < 16) ? 2 * p : 2 * p + 1);
            int n = jj * 8 + (lane & 7);
            int g = 2 * t + ((lane >> 3) & 1);
            uint32_t r4[4];
            ldsm4(r4, sb + OFF_W1L + boff(n, g));
            bb[2 * p][0] = r4[0]; bb[2 * p][1] = r4[1];
            bb[2 * p + 1][0] = r4[2]; bb[2 * p + 1][1] = r4[3];
        }
#pragma unroll
        for (int i = 0; i < 2; i++)
#pragma unroll
            for (int j = 0; j < 8; j++)
                mma16816(acc1[i][j], aH[i], bb[j]);
    }

    // ---- phase-1 epilogue: +b1, relu, fp16-split into A region ----
#pragma unroll
    for (int i = 0; i < 2; i++)
#pragma unroll
        for (int j = 0; j < 8; j++) {
            int col = wn * 64 + j * 8 + 2 * (lane & 3);
            float bv0 = b1s[col], bv1 = b1s[col + 1];
            int r0 = wm * 32 + i * 16 + (lane >> 2);
#pragma unroll
            for (int half = 0; half < 2; half++) {
                int r = r0 + half * 8;
                float v0 = fmaxf(acc1[i][j][2 * half] + bv0, 0.f);
                float v1 = fmaxf(acc1[i][j][2 * half + 1] + bv1, 0.f);
                __half h0 = __float2half_rn(v0), h1 = __float2half_rn(v1);
                uint32_t hi = (uint32_t)__half_as_ushort(h0) |
                              ((uint32_t)__half_as_ushort(h1) << 16);
                uint32_t lo = packh2(v0 - __half2float(h0), v1 - __half2float(h1));
                uint32_t off = aoff(r, col >> 3) + (col & 7) * 2;
                *(uint32_t*)(sm + OFF_AH + off) = hi;
                *(uint32_t*)(sm + OFF_AL + off) = lo;
            }
        }
    __syncthreads();

    // ---- phase-2: P = H @ W2 per 200-col N-tile, fused spline ----
    // NPAR = 800 = 4 tiles x 200 cols (8 spline channels each)   [R3 bug: was 5]
    for (int nt = 0; nt < 4; nt++) {
        const int nbase = nt * 200;
        float acc[2][7][4];
#pragma unroll
        for (int i = 0; i < 2; i++)
#pragma unroll
            for (int t = 0; t < 7; t++)
#pragma unroll
                for (int c = 0; c < 4; c++) acc[i][t][c] = 0.f;

        // load chunk 0 into buf 0
#pragma unroll
        for (int s = 0; s < 4; s++) {
            int i = tid + s * 512;
            if (i < 1600) {
                int split = i >= 800, ii = i - split * 800;
                int n = ii >> 2, g = ii & 3;
                const __half* src = split ? g_W2l : g_W2h;
                uint4 v = *(const uint4*)(src + (size_t)(nbase + n) * HID + g * 8);
                *(uint4*)(sm + OFF_U + split * 12800 + boff(n, g)) = v;
            }
        }
        __syncthreads();

        for (int kc = 0; kc < 8; kc++) {
            const uint32_t bufhi = OFF_U + (kc & 1) * BUFSZ;
            const uint32_t buflo = bufhi + 12800;

            // LDG-prefetch next chunk
            uint4 pf[4];
            if (kc < 7) {
#pragma unroll
                for (int s = 0; s < 4; s++) {
                    int i = tid + s * 512;
                    if (i < 1600) {
                        int split = i >= 800, ii = i - split * 800;
                        int n = ii >> 2, g = ii & 3;
                        const __half* src = split ? g_W2l : g_W2h;
                        pf[s] = *(const uint4*)(src + (size_t)(nbase + n) * HID +
                                                (kc + 1) * 32 + g * 8);
                    }
                }
            }

#pragma unroll
            for (int tt = 0; tt < 2; tt++) {
                const int tg = kc * 2 + tt;
                uint32_t aH[2][4], aL[2][4], bb[7][2];
#pragma unroll
                for (int i = 0; i < 2; i++) {
                    int r = wm * 32 + i * 16 + (lane & 15);
                    int g = 2 * tg + (lane >> 4);
                    ldsm4(aH[i], sb + OFF_AH + aoff(r, g));
                }
#pragma unroll
                for (int p = 0; p < 4; p++) {
                    int ta = 2 * p, tb2 = (2 * p + 1 < 7) ? 2 * p + 1 : 6;
                    int t = (lane < 16) ? ta : tb2;
                    int j = wn + 4 * t; if (j > 24) j = 24;
                    int n = j * 8 + (lane & 7);
                    int g = 2 * tt + ((lane >> 3) & 1);
                    uint32_t r4[4];
                    ldsm4(r4, sb + bufhi + boff(n, g));
                    bb[ta][0] = r4[0]; bb[ta][1] = r4[1];
                    if (2 * p + 1 < 7) { bb[2 * p + 1][0] = r4[2]; bb[2 * p + 1][1] = r4[3]; }
                }
#pragma unroll
                for (int t = 0; t < 7; t++)
                    if (t < 6 || wn == 0) {
                        mma16816(acc[0][t], aH[0], bb[t]);
                        mma16816(acc[1][t], aH[1], bb[t]);
                    }
#pragma unroll
                for (int i = 0; i < 2; i++) {
                    int r = wm * 32 + i * 16 + (lane & 15);
                    int g = 2 * tg + (lane >> 4);
                    ldsm4(aL[i], sb + OFF_AL + aoff(r, g));
                }
#pragma unroll
                for (int t = 0; t < 7; t++)
                    if (t < 6 || wn == 0) {
                        mma16816(acc[0][t], aL[0], bb[t]);
                        mma16816(acc[1][t], aL[1], bb[t]);
                    }
#pragma unroll
                for (int p = 0; p < 4; p++) {
                    int ta = 2 * p, tb2 = (2 * p + 1 < 7) ? 2 * p + 1 : 6;
                    int t = (lane < 16) ? ta : tb2;
                    int j = wn + 4 * t; if (j > 24) j = 24;
                    int n = j * 8 + (lane & 7);
                    int g = 2 * tt + ((lane >> 3) & 1);
                    uint32_t r4[4];
                    ldsm4(r4, sb + buflo + boff(n, g));
                    bb[ta][0] = r4[0]; bb[ta][1] = r4[1];
                    if (2 * p + 1 < 7) { bb[2 * p + 1][0] = r4[2]; bb[2 * p + 1][1] = r4[3]; }
                }
#pragma unroll
                for (int t = 0; t < 7; t++)
                    if (t < 6 || wn == 0) {
                        mma16816(acc[0][t], aH[0], bb[t]);
                        mma16816(acc[1][t], aH[1], bb[t]);
                    }
            }

            // store prefetched chunk to other buffer
            if (kc < 7) {
                char* dstb = sm + OFF_U + ((kc + 1) & 1) * BUFSZ;
#pragma unroll
                for (int s = 0; s < 4; s++) {
                    int i = tid + s * 512;
                    if (i < 1600) {
                        int split = i >= 800, ii = i - split * 800;
                        int n = ii >> 2, g = ii & 3;
                        *(uint4*)(dstb + split * 12800 + boff(n, g)) = pf[s];
                    }
                }
            }
            __syncthreads();
        }

        // ---- epilogue: stage + spline, 64 rows at a time ----
        for (int mh = 0; mh < 2; mh++) {
            if ((wm >> 1) == mh) {
                int rloc = (wm & 1) * 32;
#pragma unroll
                for (int i = 0; i < 2; i++)
#pragma unroll
                    for (int t = 0; t < 7; t++)
                        if (t < 6 || wn == 0) {
                            int col = (wn + 4 * t) * 8 + 2 * (lane & 3);
                            int r0 = rloc + i * 16 + (lane >> 2);
                            *(float2*)&stage[r0 * 200 + col] =
                                make_float2(acc[i][t][0], acc[i][t][1]);
                            *(float2*)&stage[(r0 + 8) * 200 + col] =
                                make_float2(acc[i][t][2], acc[i][t][3]);
                        }
            }
            __syncthreads();

            {
                const int rl = tid >> 3, lc = tid & 7;
                const int ch = nt * 8 + lc;
                const float* sp = &stage[rl * 200 + lc * 25];
                const float* bp = &b2s[ch * 25];
                float pr[25];
#pragma unroll
                for (int j = 0; j < 25; j++) pr[j] = sp[j] + bp[j];

                // widths
                float mw = pr[0];
#pragma unroll
                for (int j = 1; j < 8; j++) mw = fmaxf(mw, pr[j]);
                float ew[8], sw = 0.f;
#pragma unroll
                for (int j = 0; j < 8; j++) { ew[j] = expf(pr[j] - mw); sw += ew[j]; }
                float invw = 1.f / sw;
                float w[8];
#pragma unroll
                for (int j = 0; j < 8; j++) w[j] = MINW + (1.f - MINW * 8.f) * ew[j] * invw;
                float cw[9]; cw[0] = 0.f;
#pragma unroll
                for (int j = 0; j < 8; j++) cw[j + 1] = cw[j] + w[j];
                float itw = 1.f / fmaxf(cw[8], EPSC);
#pragma unroll
                for (int j = 0; j < 9; j++) cw[j] *= itw;
#pragma unroll
                for (int j = 0; j < 8; j++) w[j] = cw[j + 1] - cw[j];

                // heights
                float mhh = pr[8];
#pragma unroll
                for (int j = 1; j < 8; j++) mhh = fmaxf(mhh, pr[8 + j]);
                float eh[8], sh = 0.f;
#pragma unroll
                for (int j = 0; j < 8; j++) { eh[j] = expf(pr[8 + j] - mhh); sh += eh[j]; }
                float invh = 1.f / sh;
                float hh[8];
#pragma unroll
                for (int j = 0; j < 8; j++) hh[j] = MINW + (1.f - MINW * 8.f) * eh[j] * invh;
                float chh[9]; chh[0] = 0.f;
#pragma unroll
                for (int j = 0; j < 8; j++) chh[j + 1] = chh[j] + hh[j];
                float ith = 1.f / fmaxf(chh[8], EPSC);
#pragma unroll
                for (int j = 0; j < 9; j++) chh[j] *= ith;
#pragma unroll
                for (int j = 0; j < 8; j++) hh[j] = chh[j + 1] - chh[j];

                // derivatives (softplus)
                float d[9];
#pragma unroll
                for (int j = 0; j < 9; j++) {
                    float u = pr[16 + j];
                    d[j] = MIND + fmaxf(u, 0.f) + log1pf(expf(-fabsf(u)));
                }

                const int grow = rbase + mh * 64 + rl;
                const float x = X[(size_t)grow * D_IN + 32 + ch];
                const bool inside = (x >= -10.f) && (x <= 10.f);
                float xs = fminf(fmaxf((x + 10.f) * 0.05f, 0.f), 1.f);

                float xk = cw[0], wk = w[0], yk = chh[0], hk = hh[0], dk = d[0], dk1 = d[1];
#pragma unroll
                for (int i = 0; i < 8; i++) {
                    if (xs >= cw[i]) {
                        xk = cw[i]; wk = w[i]; yk = chh[i]; hk = hh[i];
                        dk = d[i]; dk1 = d[i + 1];
                    }
                }
                float t   = fminf(fmaxf((xs - xk) / (wk + EPSC), 0.f), 1.f);
                float a   = (hk + EPSC) / (wk + EPSC);
                float omt = 1.f - t;
                float num = a * t * t + dk * t * omt;
                float den = a + (dk + dk1 - 2.f * a) * t * omt;
                float s   = num / (den + EPSC);
                float y   = (yk + hk * s) * 20.f - 10.f;
                float dnum = a * a * (dk1 * t * t + 2.f * a * t * omt + dk * omt * omt);
                float dydx = dnum / (den * den + EPSC);
                float ladv = logf(fmaxf(dydx, 1e-12f));

                out[(size_t)grow * D_IN + 32 + ch] = inside ? y : x;
                float lv = inside ? ladv : 0.f;
                lv += __shfl_xor_sync(0xffffffffu, lv, 1);
                lv += __shfl_xor_sync(0xffffffffu, lv, 2);
                lv += __shfl_xor_sync(0xffffffffu, lv, 4);
                if ((lane & 7) == 0) lad[mh * 64 + rl] += lv;
            }
            __syncthreads();
        }
    }

    if (tid < 128) out[(size_t)B * D_IN + rbase + tid] = lad[tid];
}

// ---------------------------------------------------------------------------
extern "C" void kernel_launch(void* const* d_in, const int* in_sizes, int n_in,
                              void* d_out, int out_size)
{
    const float* X  = (const float*)d_in[0];
    const float* W1 = (const float*)d_in[1];
    const float* b1 = (const float*)d_in[2];
    const float* W2 = (const float*)d_in[3];
    const float* b2 = (const float*)d_in[4];
    float* out = (float*)d_out;

    const int B = in_sizes[0] / D_IN;

    cudaFuncSetAttribute(kmain, cudaFuncAttributeMaxDynamicSharedMemorySize, SMEM_TOT);

    kprep<<<NPAR + HID, 256>>>(W1, W2);
    kmain<<<B / 128, 512, SMEM_TOT>>>(X, b1, b2, out, B);
}